// round 14
// baseline (speedup 1.0000x reference)
#include <cuda_runtime.h>
#include <cuda_bf16.h>
#include <math.h>
#include <stdint.h>

// Problem dims
#define NT    512
#define NBATCH 64
#define NIN   512
#define NH    1024
#define NOUT  128
#define KC 32          // fp32 gemm64 K-chunk (logits only)

// Precompute mma_tile tiling: K-chunk 64, smem row stride 72 bf16
#define KCH  64
#define SROW 72

// Step kernel: K-chunk 128, double-buffered; bf16 row stride 136 (272B, odd*16B)
#define KS2  128
#define SR2  136
#define BUF_A (64 * SR2)
#define BUF_B (128 * SR2)
#define BUF_ELEMS (BUF_A + BUF_B)
#define STEP_SMEM (2 * BUF_ELEMS * 2)   // 104448 B

// ----------------------------------------------------------------------------
// Scratch (__device__ globals)
// g_P[t][b][j]: j<1024 ha accumulator, j>=1024 pre-relu u accumulator.
//   precompute STOREs x-part + bias (replay-idempotent); step ph1 adds h-part
//   in place (single producer per element, no atomics).
// g_HB[t][b][j]: hb accumulator (pre-init b_u2h); step ph2 adds in place.
// g_Wh: [2048 j][1536 k] bf16 of [W_i2h; W_i2u]; g_Wu: [1024 j][2048 k].
// ----------------------------------------------------------------------------
__device__ float g_P [(size_t)NT * NBATCH * 2048];         // 256 MB
__device__ float g_HB[(size_t)NT * NBATCH * NH];           // 128 MB
__device__ float g_OUTACC[NBATCH * NOUT];
__device__ __nv_bfloat16 g_Wh[(size_t)2048 * 1536];
__device__ __nv_bfloat16 g_Wu[(size_t)1024 * 2048];

// ============================================================================
// MMA helpers
// ============================================================================
__device__ __forceinline__ uint32_t s2u(const void* p) {
    return (uint32_t)__cvta_generic_to_shared(p);
}
__device__ __forceinline__ void ldsm4(uint32_t* r, uint32_t addr) {
    asm volatile("ldmatrix.sync.aligned.m8n8.x4.shared.b16 {%0,%1,%2,%3}, [%4];"
        : "=r"(r[0]), "=r"(r[1]), "=r"(r[2]), "=r"(r[3]) : "r"(addr));
}
__device__ __forceinline__ void mma_bf16(float* d, const uint32_t* a,
                                         uint32_t b0, uint32_t b1) {
    asm volatile(
        "mma.sync.aligned.m16n8k16.row.col.f32.bf16.bf16.f32 "
        "{%0,%1,%2,%3},{%4,%5,%6,%7},{%8,%9},{%0,%1,%2,%3};"
        : "+f"(d[0]), "+f"(d[1]), "+f"(d[2]), "+f"(d[3])
        : "r"(a[0]), "r"(a[1]), "r"(a[2]), "r"(a[3]), "r"(b0), "r"(b1));
}

// ----------------------------------------------------------------------------
// mma_tile (round-6 proven, STORE path only): O[64][128] = A@W^T + bias.
// Used by precompute.
// ----------------------------------------------------------------------------
__device__ __forceinline__ void mma_tile_store(
    const float* __restrict__ A, int lda,
    const __nv_bfloat16* __restrict__ W, int ldw, int Klen,
    float* __restrict__ O, int ldo,
    const float* __restrict__ bias,
    __nv_bfloat16* __restrict__ sm)
{
    __nv_bfloat16* sA = sm;
    __nv_bfloat16* sB = sm + 64 * SROW;

    const int tid  = threadIdx.x;
    const int lane = tid & 31;
    const int wid  = tid >> 5;
    const int m0   = (wid & 1) * 32;
    const int n0   = (wid >> 1) * 32;

    int ar[4], ac[4], br[4], bq[4];
    const float* pA[4];
    const __nv_bfloat16* pB[4];
    #pragma unroll
    for (int i = 0; i < 4; ++i) {
        int p = tid + i * 256;
        ar[i] = p >> 4;  ac[i] = (p & 15) << 2;
        pA[i] = A + (size_t)ar[i] * lda + ac[i];
        br[i] = p >> 3;  bq[i] = (p & 7) << 3;
        pB[i] = W + (size_t)br[i] * ldw + bq[i];
    }
    const uint32_t aOff = (uint32_t)((lane & 15) * (SROW * 2) + ((lane >> 4) << 4));
    const uint32_t bOff = (uint32_t)(((lane & 7) + ((lane >> 4) << 3)) * (SROW * 2)
                                     + (((lane >> 3) & 1) << 4));
    const uint32_t uA = s2u(sA) + aOff;
    const uint32_t uB = s2u(sB) + bOff;

    float acc[2][4][4];
    #pragma unroll
    for (int mi = 0; mi < 2; ++mi)
        #pragma unroll
        for (int ni = 0; ni < 4; ++ni)
            #pragma unroll
            for (int r = 0; r < 4; ++r) acc[mi][ni][r] = 0.0f;

    float4 aR[4]; uint4 bR[4];
    #pragma unroll
    for (int i = 0; i < 4; ++i) {
        aR[i] = *(const float4*)(pA[i]);
        bR[i] = *(const uint4*)(pB[i]);
    }

    const int nch = Klen / KCH;
    for (int c = 0; c < nch; ++c) {
        __syncthreads();
        #pragma unroll
        for (int i = 0; i < 4; ++i) {
            float4 v = aR[i];
            __nv_bfloat162* da = (__nv_bfloat162*)&sA[ar[i] * SROW + ac[i]];
            da[0] = __halves2bfloat162(__float2bfloat16_rn(v.x), __float2bfloat16_rn(v.y));
            da[1] = __halves2bfloat162(__float2bfloat16_rn(v.z), __float2bfloat16_rn(v.w));
            *(uint4*)&sB[br[i] * SROW + bq[i]] = bR[i];
        }
        __syncthreads();
        if (c + 1 < nch) {
            #pragma unroll
            for (int i = 0; i < 4; ++i) {
                aR[i] = *(const float4*)(pA[i] + (c + 1) * KCH);
                bR[i] = *(const uint4*)(pB[i] + (c + 1) * KCH);
            }
        }
        #pragma unroll
        for (int kk = 0; kk < 4; ++kk) {
            const uint32_t kb = kk * 32;
            uint32_t ah[2][4], bh[2][4];
            ldsm4(ah[0], uA + (m0 +  0) * (SROW * 2) + kb);
            ldsm4(ah[1], uA + (m0 + 16) * (SROW * 2) + kb);
            ldsm4(bh[0], uB + (n0 +  0) * (SROW * 2) + kb);
            ldsm4(bh[1], uB + (n0 + 16) * (SROW * 2) + kb);
            #pragma unroll
            for (int mi = 0; mi < 2; ++mi)
                #pragma unroll
                for (int ni = 0; ni < 4; ++ni) {
                    const int np = ni >> 1, hf = (ni & 1) << 1;
                    mma_bf16(acc[mi][ni], ah[mi], bh[np][hf], bh[np][hf + 1]);
                }
        }
    }

    const int g  = lane >> 2;
    const int tg = lane & 3;
    #pragma unroll
    for (int mi = 0; mi < 2; ++mi)
        #pragma unroll
        for (int ni = 0; ni < 4; ++ni) {
            const int brow = m0 + mi * 16 + g;
            const int jc   = n0 + ni * 8 + tg * 2;
            float b0 = bias[jc], b1 = bias[jc + 1];
            *(float2*)(O + (size_t)brow * ldo + jc) =
                make_float2(acc[mi][ni][0] + b0, acc[mi][ni][1] + b1);
            *(float2*)(O + (size_t)(brow + 8) * ldo + jc) =
                make_float2(acc[mi][ni][2] + b0, acc[mi][ni][3] + b1);
        }
}

// ============================================================================
// Weight convert (unchanged): fp32 -> bf16, pure stores, 32-bit indexing.
// ============================================================================
__global__ void __launch_bounds__(256)
wconv_kernel(const float* __restrict__ W_i2h, const float* __restrict__ W_i2u,
             const float* __restrict__ W_u2h)
{
    const int b = blockIdx.x;
    if (b < 3072) {
        unsigned base = (unsigned)b * 1024u;
        unsigned j = base / 1536u;
        unsigned k = base - j * 1536u;
        const float* src = (j < NH) ? (W_i2h + (size_t)j * 1536 + k)
                                    : (W_i2u + (size_t)(j - NH) * 1536 + k);
        __nv_bfloat16* dst = g_Wh + base;
        unsigned t4 = threadIdx.x * 4u;
        unsigned rem = 1536u - k;
        #pragma unroll
        for (int e = 0; e < 4; ++e) {
            unsigned idx = t4 + e;
            float v;
            if (idx < rem) v = src[idx];
            else {
                unsigned j2 = j + 1 + (idx - rem) / 1536u;
                unsigned k2 = (idx - rem) % 1536u;
                v = (j2 < NH) ? W_i2h[(size_t)j2 * 1536 + k2]
                              : W_i2u[(size_t)(j2 - NH) * 1536 + k2];
            }
            dst[idx] = __float2bfloat16_rn(v);
        }
    } else {
        unsigned base = (unsigned)(b - 3072) * 1024u;
        unsigned t4 = threadIdx.x * 4u;
        #pragma unroll
        for (int e = 0; e < 4; ++e)
            g_Wu[base + t4 + e] = __float2bfloat16_rn(W_u2h[base + t4 + e]);
    }
}

// ============================================================================
// Precompute (unchanged): g_P[t] = x-part + bias; g_HB[t] = b_u2h; OUTACC init.
// grid (16 j-tiles, 512 t).
// ============================================================================
__global__ void __launch_bounds__(256)
precompute_kernel(const float* __restrict__ x,
                  const float* __restrict__ b_i2h, const float* __restrict__ b_i2u,
                  const float* __restrict__ b_u2h, const float* __restrict__ b_u2o)
{
    __shared__ __align__(16) __nv_bfloat16 sm[64 * SROW + 128 * SROW];
    const int jt = blockIdx.x;
    const int t  = blockIdx.y;
    const int j0 = jt * 128;

    const float* bias = (j0 < NH) ? (b_i2h + j0) : (b_i2u + (j0 - NH));
    mma_tile_store(x + (size_t)t * NBATCH * NIN, NIN,
                   g_Wh + (size_t)j0 * 1536, 1536, NIN,
                   g_P + (size_t)t * (NBATCH * 2048) + j0, 2048, bias, sm);

    if (jt < 8) {
        float* hb = g_HB + (size_t)t * (NBATCH * NH);
        for (int idx = threadIdx.x; idx < 64 * 128; idx += 256) {
            int b = idx >> 7, jj = idx & 127;
            hb[(size_t)b * NH + j0 + jj] = b_u2h[j0 + jj];
        }
    }
    if (t == 0 && jt == 15) {
        for (int idx = threadIdx.x; idx < NBATCH * NOUT; idx += 256)
            g_OUTACC[idx] = b_u2o[idx & (NOUT - 1)];
    }
}

// ============================================================================
// Step kernel K(t): 24 blocks, NO ATOMICS (single producer per output tile).
//  blocks [0,16):  ph1(t): j-tile 128, FULL K=1024 over ha(t-1);
//                  O = g_P[t]+j0, in-place add onto precomputed x-part+bias.
//  blocks [16,24): ph2(t-1) (t>=1): j-tile 128, FULL K=2048 over
//                  [relu(u(t-1)) | hb(t-2)]; in-place add onto b_u2h.
// Double-buffered K-chunks of 128, ONE __syncthreads per chunk, register
// prefetch one chunk ahead. Segment switch (relu-u -> hb) at chunk granularity.
// ============================================================================
__global__ void __launch_bounds__(256)
step_kernel(int t, const float* __restrict__ h0)
{
    extern __shared__ __align__(16) __nv_bfloat16 smb[];
    const int bid = blockIdx.x;

    const float *A1, *A2;
    int lda1, lda2, nch;
    bool relu1;
    const __nv_bfloat16* W;
    int ldw;
    float* O;
    int ldo;
    const int kswitch = 1024;   // segment boundary (multiple of KS2)

    if (bid < 16) {
        const int j0 = bid * 128;
        if (t == 0) { A1 = h0;                                   lda1 = NH;   }
        else        { A1 = g_P + (size_t)(t - 1) * 131072;       lda1 = 2048; }
        A2 = A1; lda2 = lda1; relu1 = false;
        W = g_Wh + (size_t)j0 * 1536 + NIN; ldw = 1536;
        O = g_P + (size_t)t * 131072 + j0;  ldo = 2048;
        nch = 1024 / KS2;   // 8
    } else {
        if (t < 1) return;
        const int s  = t - 1;
        const int j0 = (bid - 16) * 128;
        A1 = g_P + (size_t)s * 131072 + 1024; lda1 = 2048; relu1 = true;
        if (s == 0) { A2 = h0 + NBATCH * NH;               lda2 = NH; }
        else        { A2 = g_HB + (size_t)(s - 1) * 65536; lda2 = NH; }
        W = g_Wu + (size_t)j0 * 2048; ldw = 2048;
        O = g_HB + (size_t)s * 65536 + j0; ldo = 1024;
        nch = 2048 / KS2;   // 16
    }

    const int tid  = threadIdx.x;
    const int lane = tid & 31;
    const int wid  = tid >> 5;
    const int m0   = (wid & 1) * 32;
    const int n0   = (wid >> 1) * 32;

    // per-thread staging coordinates (8 A float4, 8 B uint4 per chunk)
    int arr[8], acc4[8], brr[8], bc8[8];
    #pragma unroll
    for (int i = 0; i < 8; ++i) {
        int p = i * 256 + tid;
        arr[i] = p >> 5;          // 0..63
        acc4[i] = (p & 31) << 2;  // A col 0..124
        brr[i] = p >> 4;          // 0..127
        bc8[i] = (p & 15) << 3;   // B col 0..120
    }

    float4 aR[8]; uint4 bR[8]; bool rl;
    // prefetch chunk 0
    {
        const int k0 = 0;
        const bool seg1 = (k0 < kswitch);
        const float* As = seg1 ? A1 : A2;
        const int ldas = seg1 ? lda1 : lda2;
        const int off = seg1 ? k0 : k0 - kswitch;
        rl = seg1 && relu1;
        #pragma unroll
        for (int i = 0; i < 8; ++i) {
            aR[i] = *(const float4*)(As + (size_t)arr[i] * ldas + off + acc4[i]);
            bR[i] = *(const uint4*)((const char*)(W + (size_t)brr[i] * ldw + k0) + bc8[i] * 2);
        }
    }
    // store chunk 0 into buffer 0
    {
        char* sAb = (char*)smb;
        char* sBb = (char*)(smb + BUF_A);
        #pragma unroll
        for (int i = 0; i < 8; ++i) {
            float4 v = aR[i];
            if (rl) {
                v.x = fmaxf(v.x, 0.f); v.y = fmaxf(v.y, 0.f);
                v.z = fmaxf(v.z, 0.f); v.w = fmaxf(v.w, 0.f);
            }
            __nv_bfloat162 lo = __halves2bfloat162(__float2bfloat16_rn(v.x), __float2bfloat16_rn(v.y));
            __nv_bfloat162 hi = __halves2bfloat162(__float2bfloat16_rn(v.z), __float2bfloat16_rn(v.w));
            uint64_t pk = (uint64_t)(*(uint32_t*)&lo) | ((uint64_t)(*(uint32_t*)&hi) << 32);
            *(uint64_t*)(sAb + arr[i] * (SR2 * 2) + acc4[i] * 2) = pk;
            *(uint4*)(sBb + brr[i] * (SR2 * 2) + bc8[i] * 2) = bR[i];
        }
    }
    __syncthreads();

    float acc[2][4][4];
    #pragma unroll
    for (int mi = 0; mi < 2; ++mi)
        #pragma unroll
        for (int ni = 0; ni < 4; ++ni)
            #pragma unroll
            for (int r = 0; r < 4; ++r) acc[mi][ni][r] = 0.0f;

    const uint32_t aOff = (uint32_t)((lane & 15) * (SR2 * 2) + ((lane >> 4) << 4));
    const uint32_t bOff = (uint32_t)(((lane & 7) + ((lane >> 4) << 3)) * (SR2 * 2)
                                     + (((lane >> 3) & 1) << 4));

    for (int c = 0; c < nch; ++c) {
        // prefetch chunk c+1 into regs (latency overlaps compute below)
        if (c + 1 < nch) {
            const int k0 = (c + 1) * KS2;
            const bool seg1 = (k0 < kswitch);
            const float* As = seg1 ? A1 : A2;
            const int ldas = seg1 ? lda1 : lda2;
            const int off = seg1 ? k0 : k0 - kswitch;
            rl = seg1 && relu1;
            #pragma unroll
            for (int i = 0; i < 8; ++i) {
                aR[i] = *(const float4*)(As + (size_t)arr[i] * ldas + off + acc4[i]);
                bR[i] = *(const uint4*)((const char*)(W + (size_t)brr[i] * ldw + k0) + bc8[i] * 2);
            }
        }
        // compute from buffer c&1
        {
            __nv_bfloat16* base = smb + (c & 1) * BUF_ELEMS;
            const uint32_t uA = s2u(base) + aOff;
            const uint32_t uB = s2u(base + BUF_A) + bOff;
            #pragma unroll
            for (int kk = 0; kk < KS2 / 16; ++kk) {
                const uint32_t kb = kk * 32;
                uint32_t ah[2][4], bh[2][4];
                ldsm4(ah[0], uA + (m0 +  0) * (SR2 * 2) + kb);
                ldsm4(ah[1], uA + (m0 + 16) * (SR2 * 2) + kb);
                ldsm4(bh[0], uB + (n0 +  0) * (SR2 * 2) + kb);
                ldsm4(bh[1], uB + (n0 + 16) * (SR2 * 2) + kb);
                #pragma unroll
                for (int mi = 0; mi < 2; ++mi)
                    #pragma unroll
                    for (int ni = 0; ni < 4; ++ni) {
                        const int np = ni >> 1, hf = (ni & 1) << 1;
                        mma_bf16(acc[mi][ni], ah[mi], bh[np][hf], bh[np][hf + 1]);
                    }
            }
        }
        // store prefetched chunk into the other buffer
        if (c + 1 < nch) {
            char* sAb = (char*)(smb + ((c + 1) & 1) * BUF_ELEMS);
            char* sBb = sAb + BUF_A * 2;
            #pragma unroll
            for (int i = 0; i < 8; ++i) {
                float4 v = aR[i];
                if (rl) {
                    v.x = fmaxf(v.x, 0.f); v.y = fmaxf(v.y, 0.f);
                    v.z = fmaxf(v.z, 0.f); v.w = fmaxf(v.w, 0.f);
                }
                __nv_bfloat162 lo = __halves2bfloat162(__float2bfloat16_rn(v.x), __float2bfloat16_rn(v.y));
                __nv_bfloat162 hi = __halves2bfloat162(__float2bfloat16_rn(v.z), __float2bfloat16_rn(v.w));
                uint64_t pk = (uint64_t)(*(uint32_t*)&lo) | ((uint64_t)(*(uint32_t*)&hi) << 32);
                *(uint64_t*)(sAb + arr[i] * (SR2 * 2) + acc4[i] * 2) = pk;
                *(uint4*)(sBb + brr[i] * (SR2 * 2) + bc8[i] * 2) = bR[i];
            }
        }
        __syncthreads();
    }

    // ---- epilogue: in-place add (NO atomics; single producer per element) ----
    const int g  = lane >> 2;
    const int tg = lane & 3;
    #pragma unroll
    for (int mi = 0; mi < 2; ++mi)
        #pragma unroll
        for (int ni = 0; ni < 4; ++ni) {
            const int brow = m0 + mi * 16 + g;
            const int jc   = n0 + ni * 8 + tg * 2;
            float2* d0 = (float2*)(O + (size_t)brow * ldo + jc);
            float2* d1 = (float2*)(O + (size_t)(brow + 8) * ldo + jc);
            float2 o0 = *d0, o1 = *d1;
            *d0 = make_float2(o0.x + acc[mi][ni][0], o0.y + acc[mi][ni][1]);
            *d1 = make_float2(o1.x + acc[mi][ni][2], o1.y + acc[mi][ni][3]);
        }
}

// ============================================================================
// fp32 SIMT 64x64 GEMM for the one-off logits (unchanged)
// ============================================================================
template<bool RELU>
__device__ __forceinline__ void gemm64(
    float* __restrict__ smem,
    const float* __restrict__ A, int lda,
    const float* __restrict__ W, int ldw,
    int Klen, float* __restrict__ O, int ldo)
{
    float (*sA)[68] = (float (*)[68])smem;
    float (*sW)[68] = (float (*)[68])(smem + KC * 68);
    const int tid = threadIdx.x;
    const int row = tid >> 2;
    const int q   = tid & 3;
    const int jt  = (tid & 15) << 2;
    const int bt  = (tid >> 4) << 2;

    float acc[4][4];
    #pragma unroll
    for (int i = 0; i < 4; ++i)
        #pragma unroll
        for (int j = 0; j < 4; ++j) acc[i][j] = 0.0f;

    const float* pa = A + (size_t)row * lda + q * 4;
    const float* pw = W + (size_t)row * ldw + q * 4;
    float4 a0 = *(const float4*)(pa);
    float4 a1 = *(const float4*)(pa + 16);
    float4 w0 = *(const float4*)(pw);
    float4 w1 = *(const float4*)(pw + 16);

    const int nch = Klen / KC;
    for (int c = 0; c < nch; ++c) {
        if (RELU) {
            a0.x = fmaxf(a0.x, 0.f); a0.y = fmaxf(a0.y, 0.f);
            a0.z = fmaxf(a0.z, 0.f); a0.w = fmaxf(a0.w, 0.f);
            a1.x = fmaxf(a1.x, 0.f); a1.y = fmaxf(a1.y, 0.f);
            a1.z = fmaxf(a1.z, 0.f); a1.w = fmaxf(a1.w, 0.f);
        }
        __syncthreads();
        {
            int kq = q * 4;
            sA[kq + 0][row] = a0.x; sA[kq + 1][row] = a0.y;
            sA[kq + 2][row] = a0.z; sA[kq + 3][row] = a0.w;
            sA[kq + 16][row] = a1.x; sA[kq + 17][row] = a1.y;
            sA[kq + 18][row] = a1.z; sA[kq + 19][row] = a1.w;
            sW[kq + 0][row] = w0.x; sW[kq + 1][row] = w0.y;
            sW[kq + 2][row] = w0.z; sW[kq + 3][row] = w0.w;
            sW[kq + 16][row] = w1.x; sW[kq + 17][row] = w1.y;
            sW[kq + 18][row] = w1.z; sW[kq + 19][row] = w1.w;
        }
        __syncthreads();
        if (c + 1 < nch) {
            const float* na = pa + (c + 1) * KC;
            const float* nw = pw + (c + 1) * KC;
            a0 = *(const float4*)(na);
            a1 = *(const float4*)(na + 16);
            w0 = *(const float4*)(nw);
            w1 = *(const float4*)(nw + 16);
        }
        #pragma unroll
        for (int k = 0; k < KC; ++k) {
            float4 av = *(const float4*)&sA[k][bt];
            float4 wv = *(const float4*)&sW[k][jt];
            float a[4] = {av.x, av.y, av.z, av.w};
            float w[4] = {wv.x, wv.y, wv.z, wv.w};
            #pragma unroll
            for (int bi = 0; bi < 4; ++bi)
                #pragma unroll
                for (int ji = 0; ji < 4; ++ji)
                    acc[bi][ji] = fmaf(a[bi], w[ji], acc[bi][ji]);
        }
    }
    #pragma unroll
    for (int bi = 0; bi < 4; ++bi)
        #pragma unroll
        for (int ji = 0; ji < 4; ++ji)
            atomicAdd(O + (size_t)(bt + bi) * ldo + (jt + ji), acc[bi][ji]);
}

__global__ void __launch_bounds__(256)
logits_kernel(const float* __restrict__ W_u2o)
{
    __shared__ float smem[2 * KC * 68];
    const int o0 = (blockIdx.x >> 4) * 64;
    const int k0 = (blockIdx.x & 15) * 128;
    const int tl = NT - 1;
    const float* W = W_u2o + (size_t)o0 * (2 * NH) + k0;
    float* O = g_OUTACC + o0;
    if (k0 < NH) {
        const float* A = g_P + (size_t)tl * (NBATCH * 2048) + NH + k0;
        gemm64<true>(smem, A, 2048, W, 2 * NH, 128, O, NOUT);
    } else {
        const float* A = g_HB + (size_t)(tl - 1) * (NBATCH * NH) + (k0 - NH);
        gemm64<false>(smem, A, NH, W, 2 * NH, 128, O, NOUT);
    }
}

__global__ void __launch_bounds__(256)
softmax_kernel(float* __restrict__ d_out)
{
    const int lane = threadIdx.x & 31;
    const int wid  = threadIdx.x >> 5;
    for (int b = wid; b < NBATCH; b += 8) {
        const float* rowp = g_OUTACC + (size_t)b * NOUT;
        float m = -INFINITY;
        for (int o = lane; o < NOUT; o += 32) m = fmaxf(m, rowp[o]);
        #pragma unroll
        for (int off = 16; off; off >>= 1) m = fmaxf(m, __shfl_xor_sync(0xFFFFFFFFu, m, off));
        float s = 0.0f;
        for (int o = lane; o < NOUT; o += 32) s += expf(rowp[o] - m);
        #pragma unroll
        for (int off = 16; off; off >>= 1) s += __shfl_xor_sync(0xFFFFFFFFu, s, off);
        float lse = logf(s) + m;
        for (int o = lane; o < NOUT; o += 32)
            d_out[(size_t)b * NOUT + o] = rowp[o] - lse;
    }
}

// ============================================================================
// Launch. Inputs: x, h0, W_i2h, b_i2h, W_i2u, b_i2u, W_u2h, b_u2h, W_u2o, b_u2o
// ============================================================================
extern "C" void kernel_launch(void* const* d_in, const int* in_sizes, int n_in,
                              void* d_out, int out_size)
{
    const float* x     = (const float*)d_in[0];
    const float* h0    = (const float*)d_in[1];
    const float* W_i2h = (const float*)d_in[2];
    const float* b_i2h = (const float*)d_in[3];
    const float* W_i2u = (const float*)d_in[4];
    const float* b_i2u = (const float*)d_in[5];
    const float* W_u2h = (const float*)d_in[6];
    const float* b_u2h = (const float*)d_in[7];
    const float* W_u2o = (const float*)d_in[8];
    const float* b_u2o = (const float*)d_in[9];
    float* out = (float*)d_out;

    cudaFuncSetAttribute(step_kernel,
                         cudaFuncAttributeMaxDynamicSharedMemorySize, STEP_SMEM);

    wconv_kernel<<<5120, 256>>>(W_i2h, W_i2u, W_u2h);
    dim3 gpre(16, NT);
    precompute_kernel<<<gpre, 256>>>(x, b_i2h, b_i2u, b_u2h, b_u2o);
    for (int t = 0; t < NT; ++t)
        step_kernel<<<24, 256, STEP_SMEM>>>(t, h0);
    logits_kernel<<<32, 256>>>(W_u2o);
    softmax_kernel<<<1, 256>>>(out);
}